// round 2
// baseline (speedup 1.0000x reference)
#include <cuda_runtime.h>

#define N_NODES 50000
#define E_EDGES 800000
#define DIM 256

// Scratch (static device globals — no allocation allowed)
__device__ float g_agg[N_NODES * DIM];
__device__ float g_h1[N_NODES * DIM];
__device__ float g_h2[N_NODES * DIM];

// ---------------------------------------------------------------------------
// Zero-fill (exactly N*DIM = 12,800,000 floats = 3,200,000 float4)
// ---------------------------------------------------------------------------
__global__ void zero_kernel(float4* __restrict__ p) {
    int i = blockIdx.x * blockDim.x + threadIdx.x;
    if (i < (N_NODES * DIM) / 4) {
        p[i] = make_float4(0.f, 0.f, 0.f, 0.f);
    }
}

// ---------------------------------------------------------------------------
// Edge scatter: agg[dst,:] += x[src,:]. One warp per edge; each lane handles
// 8 floats as 2 float4 loads + 8 atomicAdds.
// edge_index arrives as int32 (JAX x64 disabled downgrades int64 -> int32).
// ---------------------------------------------------------------------------
__global__ void scatter_kernel(const float* __restrict__ x,
                               const int* __restrict__ ei,
                               float* __restrict__ agg) {
    int warp = (blockIdx.x * blockDim.x + threadIdx.x) >> 5;
    int lane = threadIdx.x & 31;
    if (warp >= E_EDGES) return;
    int src = ei[warp];
    int dst = ei[E_EDGES + warp];
    if ((unsigned)src >= N_NODES || (unsigned)dst >= N_NODES) return;
    const float4* xs = (const float4*)(x + (size_t)src * DIM);
    float* ad = agg + (size_t)dst * DIM;
#pragma unroll
    for (int i = 0; i < 2; i++) {
        float4 v = xs[lane + i * 32];
        int base = (lane + i * 32) * 4;
        atomicAdd(ad + base + 0, v.x);
        atomicAdd(ad + base + 1, v.y);
        atomicAdd(ad + base + 2, v.z);
        atomicAdd(ad + base + 3, v.w);
    }
}

// ---------------------------------------------------------------------------
// Fused GEMM + bias + ELU:
//   out[i,:] = ELU( agg[i,:] @ Wrel + x[i,:] @ Wroot + b )
// Implemented as virtual [M,512] x [512,256] GEMM. 64x64 tile, BK=16,
// 256 threads, 4x4 per thread, fp32.
// ---------------------------------------------------------------------------
__global__ void fused_gemm_elu(const float* __restrict__ xin,
                               const float* __restrict__ agg,
                               const float* __restrict__ Wrel,
                               const float* __restrict__ Wroot,
                               const float* __restrict__ bias,
                               float* __restrict__ out) {
    __shared__ float As[16][64];
    __shared__ float Bs[16][64];

    int tid = threadIdx.x;
    int tx = tid & 15;       // 0..15 -> 4 output cols each
    int ty = tid >> 4;       // 0..15 -> 4 output rows each
    int rowBase = blockIdx.y * 64;
    int colBase = blockIdx.x * 64;

    float acc[4][4] = {};

    for (int k0 = 0; k0 < 512; k0 += 16) {
        const float* A = (k0 < 256) ? agg : xin;
        const float* B = (k0 < 256) ? Wrel : Wroot;
        int kc = k0 & 255;

        // Load A tile: 64 rows x 16 k-cols (transposed into As[k][row])
#pragma unroll
        for (int l = 0; l < 4; l++) {
            int i = tid + l * 256;
            int r = i >> 4, c = i & 15;
            int row = rowBase + r;
            As[c][r] = (row < N_NODES) ? A[(size_t)row * 256 + kc + c] : 0.f;
        }
        // Load B tile: 16 k-rows x 64 cols (coalesced)
#pragma unroll
        for (int l = 0; l < 4; l++) {
            int i = tid + l * 256;
            int r = i >> 6, c = i & 63;
            Bs[r][c] = B[(size_t)(kc + r) * 256 + colBase + c];
        }
        __syncthreads();

#pragma unroll
        for (int kk = 0; kk < 16; kk++) {
            float a[4], bv[4];
#pragma unroll
            for (int i = 0; i < 4; i++) a[i] = As[kk][ty * 4 + i];
#pragma unroll
            for (int j = 0; j < 4; j++) bv[j] = Bs[kk][tx * 4 + j];
#pragma unroll
            for (int i = 0; i < 4; i++)
#pragma unroll
                for (int j = 0; j < 4; j++)
                    acc[i][j] += a[i] * bv[j];
        }
        __syncthreads();
    }

#pragma unroll
    for (int i = 0; i < 4; i++) {
        int row = rowBase + ty * 4 + i;
        if (row >= N_NODES) continue;
#pragma unroll
        for (int j = 0; j < 4; j++) {
            int col = colBase + tx * 4 + j;
            float v = acc[i][j] + bias[col];
            out[(size_t)row * 256 + col] = (v > 0.f) ? v : expm1f(v);
        }
    }
}

// ---------------------------------------------------------------------------
// Launch
// ---------------------------------------------------------------------------
static void run_layer(const float* in_feat, const int* ei,
                      const float* Wrel, const float* b, const float* Wroot,
                      float* agg, float* out_feat) {
    zero_kernel<<<(N_NODES * DIM / 4 + 255) / 256, 256>>>((float4*)agg);
    scatter_kernel<<<(E_EDGES * 32 + 255) / 256, 256>>>(in_feat, ei, agg);
    dim3 grid(256 / 64, (N_NODES + 63) / 64);
    fused_gemm_elu<<<grid, 256>>>(in_feat, agg, Wrel, Wroot, b, out_feat);
}

extern "C" void kernel_launch(void* const* d_in, const int* in_sizes, int n_in,
                              void* d_out, int out_size) {
    const float* x       = (const float*)d_in[0];
    const int*   ei      = (const int*)d_in[1];
    const float* W1_rel  = (const float*)d_in[2];
    const float* b1      = (const float*)d_in[3];
    const float* W1_root = (const float*)d_in[4];
    const float* W2_rel  = (const float*)d_in[5];
    const float* b2      = (const float*)d_in[6];
    const float* W2_root = (const float*)d_in[7];
    const float* W3_rel  = (const float*)d_in[8];
    const float* b3      = (const float*)d_in[9];
    const float* W3_root = (const float*)d_in[10];
    float* out = (float*)d_out;

    float *agg, *h1, *h2;
    cudaGetSymbolAddress((void**)&agg, g_agg);
    cudaGetSymbolAddress((void**)&h1, g_h1);
    cudaGetSymbolAddress((void**)&h2, g_h2);

    run_layer(x,  ei, W1_rel, b1, W1_root, agg, h1);
    run_layer(h1, ei, W2_rel, b2, W2_root, agg, h2);
    run_layer(h2, ei, W3_rel, b3, W3_root, agg, out);
}

// round 3
// speedup vs baseline: 1.7405x; 1.7405x over previous
#include <cuda_runtime.h>

#define N_NODES 50000
#define E_EDGES 800000
#define DIM 256

// Scratch (static device globals — no allocation allowed)
__device__ float g_agg[N_NODES * DIM];
__device__ float g_h1[N_NODES * DIM];
__device__ float g_h2[N_NODES * DIM];
__device__ int   g_cnt[N_NODES];
__device__ int   g_rowptr[N_NODES + 1];
__device__ int   g_cursor[N_NODES];
__device__ int   g_srcs[E_EDGES];

// ---------------------------------------------------------------------------
// CSR build: histogram of dst, exclusive scan, fill sorted src list.
// edge_index is int32: [0:E)=src, [E:2E)=dst.
// ---------------------------------------------------------------------------
__global__ void zero_cnt_kernel(int* __restrict__ cnt) {
    int i = blockIdx.x * blockDim.x + threadIdx.x;
    if (i < N_NODES) cnt[i] = 0;
}

__global__ void hist_kernel(const int* __restrict__ ei, int* __restrict__ cnt) {
    int e = blockIdx.x * blockDim.x + threadIdx.x;
    if (e < E_EDGES) {
        int d = ei[E_EDGES + e];
        if ((unsigned)d < N_NODES) atomicAdd(&cnt[d], 1);
    }
}

// Single-block exclusive scan over 50000 counts. 1024 threads x 49-item chunks.
__global__ void scan_kernel(const int* __restrict__ cnt,
                            int* __restrict__ rowptr,
                            int* __restrict__ cursor) {
    const int C = 49;
    int tid = threadIdx.x;
    int base = tid * C;

    int s = 0;
    for (int i = 0; i < C; i++) {
        int idx = base + i;
        if (idx < N_NODES) s += cnt[idx];
    }
    // block-wide inclusive scan of per-thread sums
    int lane = tid & 31, warp = tid >> 5;
    int v = s;
#pragma unroll
    for (int o = 1; o < 32; o <<= 1) {
        int n = __shfl_up_sync(0xFFFFFFFFu, v, o);
        if (lane >= o) v += n;
    }
    __shared__ int wsum[32];
    if (lane == 31) wsum[warp] = v;
    __syncthreads();
    if (warp == 0) {
        int w = wsum[lane];
#pragma unroll
        for (int o = 1; o < 32; o <<= 1) {
            int n = __shfl_up_sync(0xFFFFFFFFu, w, o);
            if (lane >= o) w += n;
        }
        wsum[lane] = w;
    }
    __syncthreads();
    int excl = v - s + (warp > 0 ? wsum[warp - 1] : 0);

    int run = excl;
    for (int i = 0; i < C; i++) {
        int idx = base + i;
        if (idx < N_NODES) {
            rowptr[idx] = run;
            cursor[idx] = run;
            run += cnt[idx];
        }
    }
    if (tid == blockDim.x - 1) rowptr[N_NODES] = run;
}

__global__ void fill_kernel(const int* __restrict__ ei,
                            int* __restrict__ cursor,
                            int* __restrict__ srcs) {
    int e = blockIdx.x * blockDim.x + threadIdx.x;
    if (e < E_EDGES) {
        int d = ei[E_EDGES + e];
        int s = ei[e];
        if ((unsigned)d < N_NODES && (unsigned)s < N_NODES) {
            int p = atomicAdd(&cursor[d], 1);
            srcs[p] = s;
        }
    }
}

// ---------------------------------------------------------------------------
// CSR gather aggregation: agg[n,:] = sum_{e in [rowptr[n],rowptr[n+1])} x[srcs[e],:]
// 64 threads per node, one float4 column each. No atomics, no zero-fill needed.
// ---------------------------------------------------------------------------
__global__ void gather_agg_kernel(const float4* __restrict__ x4,
                                  const int* __restrict__ rowptr,
                                  const int* __restrict__ srcs,
                                  float4* __restrict__ agg4) {
    int node = blockIdx.x * 4 + (threadIdx.x >> 6);
    int t = threadIdx.x & 63;
    if (node >= N_NODES) return;
    int beg = rowptr[node];
    int end = rowptr[node + 1];

    float4 a0 = make_float4(0.f, 0.f, 0.f, 0.f);
    float4 a1 = make_float4(0.f, 0.f, 0.f, 0.f);

    int e = beg;
    for (; e + 4 <= end; e += 4) {
        int s0 = srcs[e + 0], s1 = srcs[e + 1], s2 = srcs[e + 2], s3 = srcs[e + 3];
        float4 v0 = x4[(size_t)s0 * 64 + t];
        float4 v1 = x4[(size_t)s1 * 64 + t];
        float4 v2 = x4[(size_t)s2 * 64 + t];
        float4 v3 = x4[(size_t)s3 * 64 + t];
        a0.x += v0.x; a0.y += v0.y; a0.z += v0.z; a0.w += v0.w;
        a1.x += v1.x; a1.y += v1.y; a1.z += v1.z; a1.w += v1.w;
        a0.x += v2.x; a0.y += v2.y; a0.z += v2.z; a0.w += v2.w;
        a1.x += v3.x; a1.y += v3.y; a1.z += v3.z; a1.w += v3.w;
    }
    for (; e < end; e++) {
        int s0 = srcs[e];
        float4 v0 = x4[(size_t)s0 * 64 + t];
        a0.x += v0.x; a0.y += v0.y; a0.z += v0.z; a0.w += v0.w;
    }
    float4 r;
    r.x = a0.x + a1.x; r.y = a0.y + a1.y; r.z = a0.z + a1.z; r.w = a0.w + a1.w;
    agg4[(size_t)node * 64 + t] = r;
}

// ---------------------------------------------------------------------------
// Fused GEMM + bias + ELU: out = ELU(agg@Wrel + x@Wroot + b)
// Virtual [M,512]x[512,256]. 128x64 tile, BK=16, 256 threads, 8x4 per thread.
// ---------------------------------------------------------------------------
__global__ void fused_gemm_elu(const float* __restrict__ xin,
                               const float* __restrict__ agg,
                               const float* __restrict__ Wrel,
                               const float* __restrict__ Wroot,
                               const float* __restrict__ bias,
                               float* __restrict__ out) {
    __shared__ float As[16][128];
    __shared__ float Bs[16][64];

    int tid = threadIdx.x;
    int tx = tid & 15;       // col group: 4 cols
    int ty = tid >> 4;       // row group: 8 rows
    int rowBase = blockIdx.y * 128;
    int colBase = blockIdx.x * 64;

    float acc[8][4] = {};

    for (int k0 = 0; k0 < 512; k0 += 16) {
        const float* A = (k0 < 256) ? agg : xin;
        const float* B = (k0 < 256) ? Wrel : Wroot;
        int kc = k0 & 255;

        // A tile: 128 rows x 16 k (transposed into As[k][row]); 8 loads/thread
#pragma unroll
        for (int l = 0; l < 8; l++) {
            int i = tid + l * 256;
            int r = i >> 4, c = i & 15;
            int row = rowBase + r;
            As[c][r] = (row < N_NODES) ? A[(size_t)row * 256 + kc + c] : 0.f;
        }
        // B tile: 16 k x 64 cols; 4 loads/thread, coalesced
#pragma unroll
        for (int l = 0; l < 4; l++) {
            int i = tid + l * 256;
            int r = i >> 6, c = i & 63;
            Bs[r][c] = B[(size_t)(kc + r) * 256 + colBase + c];
        }
        __syncthreads();

#pragma unroll
        for (int kk = 0; kk < 16; kk++) {
            float4 a0 = *(const float4*)&As[kk][ty * 8];
            float4 a1 = *(const float4*)&As[kk][ty * 8 + 4];
            float4 bv = *(const float4*)&Bs[kk][tx * 4];
            float a[8] = {a0.x, a0.y, a0.z, a0.w, a1.x, a1.y, a1.z, a1.w};
            float b[4] = {bv.x, bv.y, bv.z, bv.w};
#pragma unroll
            for (int i = 0; i < 8; i++)
#pragma unroll
                for (int j = 0; j < 4; j++)
                    acc[i][j] += a[i] * b[j];
        }
        __syncthreads();
    }

#pragma unroll
    for (int i = 0; i < 8; i++) {
        int row = rowBase + ty * 8 + i;
        if (row >= N_NODES) continue;
#pragma unroll
        for (int j = 0; j < 4; j++) {
            int col = colBase + tx * 4 + j;
            float v = acc[i][j] + bias[col];
            out[(size_t)row * 256 + col] = (v > 0.f) ? v : expm1f(v);
        }
    }
}

// ---------------------------------------------------------------------------
// Launch
// ---------------------------------------------------------------------------
static void run_layer(const float* in_feat,
                      const float* Wrel, const float* b, const float* Wroot,
                      const int* rowptr, const int* srcs,
                      float* agg, float* out_feat) {
    gather_agg_kernel<<<(N_NODES + 3) / 4, 256>>>(
        (const float4*)in_feat, rowptr, srcs, (float4*)agg);
    dim3 grid(256 / 64, (N_NODES + 127) / 128);
    fused_gemm_elu<<<grid, 256>>>(in_feat, agg, Wrel, Wroot, b, out_feat);
}

extern "C" void kernel_launch(void* const* d_in, const int* in_sizes, int n_in,
                              void* d_out, int out_size) {
    const float* x       = (const float*)d_in[0];
    const int*   ei      = (const int*)d_in[1];
    const float* W1_rel  = (const float*)d_in[2];
    const float* b1      = (const float*)d_in[3];
    const float* W1_root = (const float*)d_in[4];
    const float* W2_rel  = (const float*)d_in[5];
    const float* b2      = (const float*)d_in[6];
    const float* W2_root = (const float*)d_in[7];
    const float* W3_rel  = (const float*)d_in[8];
    const float* b3      = (const float*)d_in[9];
    const float* W3_root = (const float*)d_in[10];
    float* out = (float*)d_out;

    float *agg, *h1, *h2;
    int *cnt, *rowptr, *cursor, *srcs;
    cudaGetSymbolAddress((void**)&agg, g_agg);
    cudaGetSymbolAddress((void**)&h1, g_h1);
    cudaGetSymbolAddress((void**)&h2, g_h2);
    cudaGetSymbolAddress((void**)&cnt, g_cnt);
    cudaGetSymbolAddress((void**)&rowptr, g_rowptr);
    cudaGetSymbolAddress((void**)&cursor, g_cursor);
    cudaGetSymbolAddress((void**)&srcs, g_srcs);

    // CSR build (edge_index identical for all 3 layers)
    zero_cnt_kernel<<<(N_NODES + 255) / 256, 256>>>(cnt);
    hist_kernel<<<(E_EDGES + 255) / 256, 256>>>(ei, cnt);
    scan_kernel<<<1, 1024>>>(cnt, rowptr, cursor);
    fill_kernel<<<(E_EDGES + 255) / 256, 256>>>(ei, cursor, srcs);

    run_layer(x,  W1_rel, b1, W1_root, rowptr, srcs, agg, h1);
    run_layer(h1, W2_rel, b2, W2_root, rowptr, srcs, agg, h2);
    run_layer(h2, W3_rel, b3, W3_root, rowptr, srcs, agg, out);
}

// round 10
// speedup vs baseline: 3.0956x; 1.7786x over previous
#include <cuda_runtime.h>
#include <cuda_bf16.h>
#include <cstdint>

#define N_NODES 50000
#define E_EDGES 800000
#define DIM 256
#define KTOT 512

// ---------------------------------------------------------------------------
// Scratch (static device globals — no allocation allowed)
// ---------------------------------------------------------------------------
__device__ float g_agg[N_NODES * DIM];
__device__ float g_h1[N_NODES * DIM];
__device__ float g_h2[N_NODES * DIM];
__device__ int   g_cnt[N_NODES];
__device__ int   g_rowptr[N_NODES + 1];
__device__ int   g_cursor[N_NODES];
__device__ int   g_srcs[E_EDGES];
// Weight planes: [layer][k=512][n=256] bf16 hi/lo
__device__ __nv_bfloat16 g_Bh[3 * KTOT * DIM];
__device__ __nv_bfloat16 g_Bl[3 * KTOT * DIM];

// ---------------------------------------------------------------------------
// PTX helpers
// ---------------------------------------------------------------------------
__device__ __forceinline__ uint32_t smem_u32(const void* p) {
    uint32_t a;
    asm("{ .reg .u64 t; cvta.to.shared.u64 t, %1; cvt.u32.u64 %0, t; }"
        : "=r"(a) : "l"(p));
    return a;
}
__device__ __forceinline__ void ldm_x4(uint32_t* r, uint32_t addr) {
    asm volatile("ldmatrix.sync.aligned.m8n8.x4.shared.b16 {%0,%1,%2,%3}, [%4];"
                 : "=r"(r[0]), "=r"(r[1]), "=r"(r[2]), "=r"(r[3]) : "r"(addr));
}
__device__ __forceinline__ void ldm_x4_t(uint32_t* r, uint32_t addr) {
    asm volatile("ldmatrix.sync.aligned.m8n8.x4.trans.shared.b16 {%0,%1,%2,%3}, [%4];"
                 : "=r"(r[0]), "=r"(r[1]), "=r"(r[2]), "=r"(r[3]) : "r"(addr));
}
__device__ __forceinline__ void mma_bf16(float* c, const uint32_t* a, const uint32_t* b) {
    asm volatile("mma.sync.aligned.m16n8k16.row.col.f32.bf16.bf16.f32 "
                 "{%0,%1,%2,%3}, {%4,%5,%6,%7}, {%8,%9}, {%0,%1,%2,%3};"
                 : "+f"(c[0]), "+f"(c[1]), "+f"(c[2]), "+f"(c[3])
                 : "r"(a[0]), "r"(a[1]), "r"(a[2]), "r"(a[3]),
                   "r"(b[0]), "r"(b[1]));
}

// ---------------------------------------------------------------------------
// CSR build
// ---------------------------------------------------------------------------
__global__ void zero_cnt_kernel(int* __restrict__ cnt) {
    int i = blockIdx.x * blockDim.x + threadIdx.x;
    if (i < N_NODES) cnt[i] = 0;
}
__global__ void hist_kernel(const int* __restrict__ ei, int* __restrict__ cnt) {
    int e = blockIdx.x * blockDim.x + threadIdx.x;
    if (e < E_EDGES) {
        int d = ei[E_EDGES + e];
        if ((unsigned)d < N_NODES) atomicAdd(&cnt[d], 1);
    }
}
__global__ void scan_kernel(const int* __restrict__ cnt,
                            int* __restrict__ rowptr, int* __restrict__ cursor) {
    const int C = 49;
    int tid = threadIdx.x;
    int base = tid * C;
    int s = 0;
    for (int i = 0; i < C; i++) { int idx = base + i; if (idx < N_NODES) s += cnt[idx]; }
    int lane = tid & 31, warp = tid >> 5;
    int v = s;
#pragma unroll
    for (int o = 1; o < 32; o <<= 1) {
        int n = __shfl_up_sync(0xFFFFFFFFu, v, o);
        if (lane >= o) v += n;
    }
    __shared__ int wsum[32];
    if (lane == 31) wsum[warp] = v;
    __syncthreads();
    if (warp == 0) {
        int w = wsum[lane];
#pragma unroll
        for (int o = 1; o < 32; o <<= 1) {
            int n = __shfl_up_sync(0xFFFFFFFFu, w, o);
            if (lane >= o) w += n;
        }
        wsum[lane] = w;
    }
    __syncthreads();
    int excl = v - s + (warp > 0 ? wsum[warp - 1] : 0);
    int run = excl;
    for (int i = 0; i < C; i++) {
        int idx = base + i;
        if (idx < N_NODES) { rowptr[idx] = run; cursor[idx] = run; run += cnt[idx]; }
    }
    if (tid == blockDim.x - 1) rowptr[N_NODES] = run;
}
__global__ void fill_kernel(const int* __restrict__ ei,
                            int* __restrict__ cursor, int* __restrict__ srcs) {
    int e = blockIdx.x * blockDim.x + threadIdx.x;
    if (e < E_EDGES) {
        int d = ei[E_EDGES + e];
        int s = ei[e];
        if ((unsigned)d < N_NODES && (unsigned)s < N_NODES) {
            int p = atomicAdd(&cursor[d], 1);
            srcs[p] = s;
        }
    }
}

// ---------------------------------------------------------------------------
// Weight prep: W[k,n] -> [k][n] bf16 hi/lo planes (virtual K: Wrel then Wroot)
// ---------------------------------------------------------------------------
__global__ void prep_weights(const float* __restrict__ W1r, const float* __restrict__ W1o,
                             const float* __restrict__ W2r, const float* __restrict__ W2o,
                             const float* __restrict__ W3r, const float* __restrict__ W3o,
                             __nv_bfloat16* __restrict__ Bh, __nv_bfloat16* __restrict__ Bl) {
    int i = blockIdx.x * blockDim.x + threadIdx.x;
    if (i >= 3 * KTOT * DIM) return;
    int layer = i / (KTOT * DIM);
    int rem = i % (KTOT * DIM);
    int k = rem >> 8;         // 0..511
    int n = rem & 255;
    const float* Wr = (layer == 0) ? W1r : (layer == 1) ? W2r : W3r;
    const float* Wo = (layer == 0) ? W1o : (layer == 1) ? W2o : W3o;
    float w = (k < 256) ? Wr[k * 256 + n] : Wo[(k - 256) * 256 + n];
    __nv_bfloat16 hi = __float2bfloat16(w);
    __nv_bfloat16 lo = __float2bfloat16(w - __bfloat162float(hi));
    Bh[i] = hi;
    Bl[i] = lo;
}

// ---------------------------------------------------------------------------
// CSR gather aggregation
// ---------------------------------------------------------------------------
__global__ void gather_agg_kernel(const float4* __restrict__ x4,
                                  const int* __restrict__ rowptr,
                                  const int* __restrict__ srcs,
                                  float4* __restrict__ agg4) {
    int node = blockIdx.x * 4 + (threadIdx.x >> 6);
    int t = threadIdx.x & 63;
    if (node >= N_NODES) return;
    int beg = rowptr[node];
    int end = rowptr[node + 1];
    float4 a0 = make_float4(0.f, 0.f, 0.f, 0.f);
    float4 a1 = make_float4(0.f, 0.f, 0.f, 0.f);
    int e = beg;
    for (; e + 4 <= end; e += 4) {
        int s0 = srcs[e + 0], s1 = srcs[e + 1], s2 = srcs[e + 2], s3 = srcs[e + 3];
        float4 v0 = x4[(size_t)s0 * 64 + t];
        float4 v1 = x4[(size_t)s1 * 64 + t];
        float4 v2 = x4[(size_t)s2 * 64 + t];
        float4 v3 = x4[(size_t)s3 * 64 + t];
        a0.x += v0.x; a0.y += v0.y; a0.z += v0.z; a0.w += v0.w;
        a1.x += v1.x; a1.y += v1.y; a1.z += v1.z; a1.w += v1.w;
        a0.x += v2.x; a0.y += v2.y; a0.z += v2.z; a0.w += v2.w;
        a1.x += v3.x; a1.y += v3.y; a1.z += v3.z; a1.w += v3.w;
    }
    for (; e < end; e++) {
        int s0 = srcs[e];
        float4 v0 = x4[(size_t)s0 * 64 + t];
        a0.x += v0.x; a0.y += v0.y; a0.z += v0.z; a0.w += v0.w;
    }
    float4 r;
    r.x = a0.x + a1.x; r.y = a0.y + a1.y; r.z = a0.z + a1.z; r.w = a0.w + a1.w;
    agg4[(size_t)node * 64 + t] = r;
}

// ---------------------------------------------------------------------------
// Tensor-core GEMM (mma.sync bf16, 3-pass Markidis split) + bias + ELU.
// out[m,n] = ELU( sum_k A[m,k]*B[k,n] + bias[n] ),  A = [agg | x], K=512.
// Block 128x128, BK=32, 8 warps (warp tile 32x64).
// ---------------------------------------------------------------------------
#define AS_STRIDE 40    // bf16; 80B rows, ldmatrix conflict-free
#define BS_STRIDE 136   // bf16; 272B rows, ldmatrix conflict-free

__global__ void __launch_bounds__(256, 1)
gemm_mma(const float* __restrict__ xin, const float* __restrict__ agg,
         const __nv_bfloat16* __restrict__ BhG, const __nv_bfloat16* __restrict__ BlG,
         const float* __restrict__ bias, float* __restrict__ out) {
    __shared__ __nv_bfloat16 Ahs[128 * AS_STRIDE];
    __shared__ __nv_bfloat16 Als[128 * AS_STRIDE];
    __shared__ __nv_bfloat16 Bhs[32 * BS_STRIDE];
    __shared__ __nv_bfloat16 Bls[32 * BS_STRIDE];

    int tid = threadIdx.x;
    int wid = tid >> 5;
    int lane = tid & 31;
    int rowBase = blockIdx.y * 128;
    int colBase = blockIdx.x * 128;
    int wm = wid >> 1;       // 0..3 -> 32-row band
    int wn = wid & 1;        // 0..1 -> 64-col band

    float acc[2][8][4];
#pragma unroll
    for (int i = 0; i < 2; i++)
#pragma unroll
        for (int j = 0; j < 8; j++)
#pragma unroll
            for (int q = 0; q < 4; q++) acc[i][j][q] = 0.f;

    for (int it = 0; it < 16; it++) {
        int kglob = it * 32;
        const float* A = (it < 8) ? agg : xin;
        int kc = kglob & 255;

        // --- load B tile: 32 k-rows x 128 n-cols, hi+lo ---
#pragma unroll
        for (int p = 0; p < 2; p++) {
            int idx = tid + p * 256;        // 512 uint4 per plane
            int r = idx >> 4, c = idx & 15;
            size_t g = (size_t)(kglob + r) * 256 + colBase + c * 8;
            *(uint4*)&Bhs[r * BS_STRIDE + c * 8] = *(const uint4*)&BhG[g];
            *(uint4*)&Bls[r * BS_STRIDE + c * 8] = *(const uint4*)&BlG[g];
        }
        // --- load A tile fp32, split hi/lo bf16 ---
#pragma unroll
        for (int p = 0; p < 4; p++) {
            int idx = tid + p * 256;        // 1024 float4
            int r = idx >> 3, c4 = idx & 7;
            int row = rowBase + r;
            float4 v = make_float4(0.f, 0.f, 0.f, 0.f);
            if (row < N_NODES)
                v = *(const float4*)(A + (size_t)row * 256 + kc + c4 * 4);
            __nv_bfloat16 h0 = __float2bfloat16(v.x);
            __nv_bfloat16 h1 = __float2bfloat16(v.y);
            __nv_bfloat16 h2 = __float2bfloat16(v.z);
            __nv_bfloat16 h3 = __float2bfloat16(v.w);
            __nv_bfloat16 l0 = __float2bfloat16(v.x - __bfloat162float(h0));
            __nv_bfloat16 l1 = __float2bfloat16(v.y - __bfloat162float(h1));
            __nv_bfloat16 l2 = __float2bfloat16(v.z - __bfloat162float(h2));
            __nv_bfloat16 l3 = __float2bfloat16(v.w - __bfloat162float(h3));
            uint2 hp, lp;
            hp.x = ((uint32_t)*(unsigned short*)&h1 << 16) | *(unsigned short*)&h0;
            hp.y = ((uint32_t)*(unsigned short*)&h3 << 16) | *(unsigned short*)&h2;
            lp.x = ((uint32_t)*(unsigned short*)&l1 << 16) | *(unsigned short*)&l0;
            lp.y = ((uint32_t)*(unsigned short*)&l3 << 16) | *(unsigned short*)&l2;
            *(uint2*)&Ahs[r * AS_STRIDE + c4 * 4] = hp;
            *(uint2*)&Als[r * AS_STRIDE + c4 * 4] = lp;
        }
        __syncthreads();

        // --- compute: 2 k16 steps ---
#pragma unroll
        for (int ks = 0; ks < 2; ks++) {
            int k0 = ks * 16;
            uint32_t ah[2][4], al[2][4];
            int arow = wm * 32 + (lane & 15);
            int akk = k0 + (lane >> 4) * 8;
#pragma unroll
            for (int mb = 0; mb < 2; mb++) {
                uint32_t offH = smem_u32(&Ahs[(arow + mb * 16) * AS_STRIDE + akk]);
                uint32_t offL = smem_u32(&Als[(arow + mb * 16) * AS_STRIDE + akk]);
                ldm_x4(ah[mb], offH);
                ldm_x4(al[mb], offL);
            }
            uint32_t bh[8][2], bl[8][2];
            int brow = k0 + (lane & 15);
#pragma unroll
            for (int np = 0; np < 4; np++) {
                int ncol = wn * 64 + np * 16 + (lane >> 4) * 8;
                uint32_t rh[4], rl[4];
                ldm_x4_t(rh, smem_u32(&Bhs[brow * BS_STRIDE + ncol]));
                ldm_x4_t(rl, smem_u32(&Bls[brow * BS_STRIDE + ncol]));
                bh[np * 2][0] = rh[0]; bh[np * 2][1] = rh[1];
                bh[np * 2 + 1][0] = rh[2]; bh[np * 2 + 1][1] = rh[3];
                bl[np * 2][0] = rl[0]; bl[np * 2][1] = rl[1];
                bl[np * 2 + 1][0] = rl[2]; bl[np * 2 + 1][1] = rl[3];
            }
#pragma unroll
            for (int mb = 0; mb < 2; mb++)
#pragma unroll
                for (int nb = 0; nb < 8; nb++) {
                    mma_bf16(acc[mb][nb], ah[mb], bh[nb]);
                    mma_bf16(acc[mb][nb], ah[mb], bl[nb]);
                    mma_bf16(acc[mb][nb], al[mb], bh[nb]);
                }
        }
        __syncthreads();
    }

    // --- epilogue: bias + ELU, direct float2 stores ---
#pragma unroll
    for (int mb = 0; mb < 2; mb++) {
        int row0 = rowBase + wm * 32 + mb * 16 + (lane >> 2);
#pragma unroll
        for (int nb = 0; nb < 8; nb++) {
            int col = colBase + wn * 64 + nb * 8 + (lane & 3) * 2;
            float b0 = bias[col], b1 = bias[col + 1];
            if (row0 < N_NODES) {
                float v0 = acc[mb][nb][0] + b0;
                float v1 = acc[mb][nb][1] + b1;
                float2 r;
                r.x = (v0 > 0.f) ? v0 : expm1f(v0);
                r.y = (v1 > 0.f) ? v1 : expm1f(v1);
                *(float2*)(out + (size_t)row0 * 256 + col) = r;
            }
            int row1 = row0 + 8;
            if (row1 < N_NODES) {
                float v2 = acc[mb][nb][2] + b0;
                float v3 = acc[mb][nb][3] + b1;
                float2 r;
                r.x = (v2 > 0.f) ? v2 : expm1f(v2);
                r.y = (v3 > 0.f) ? v3 : expm1f(v3);
                *(float2*)(out + (size_t)row1 * 256 + col) = r;
            }
        }
    }
}

// ---------------------------------------------------------------------------
// Launch
// ---------------------------------------------------------------------------
static void run_layer(const float* in_feat, const __nv_bfloat16* Bh,
                      const __nv_bfloat16* Bl, const float* b,
                      const int* rowptr, const int* srcs,
                      float* agg, float* out_feat) {
    gather_agg_kernel<<<(N_NODES + 3) / 4, 256>>>(
        (const float4*)in_feat, rowptr, srcs, (float4*)agg);
    dim3 grid(2, (N_NODES + 127) / 128);
    gemm_mma<<<grid, 256>>>(in_feat, agg, Bh, Bl, b, out_feat);
}

extern "C" void kernel_launch(void* const* d_in, const int* in_sizes, int n_in,
                              void* d_out, int out_size) {
    const float* x       = (const float*)d_in[0];
    const int*   ei      = (const int*)d_in[1];
    const float* W1_rel  = (const float*)d_in[2];
    const float* b1      = (const float*)d_in[3];
    const float* W1_root = (const float*)d_in[4];
    const float* W2_rel  = (const float*)d_in[5];
    const float* b2      = (const float*)d_in[6];
    const float* W2_root = (const float*)d_in[7];
    const float* W3_rel  = (const float*)d_in[8];
    const float* b3      = (const float*)d_in[9];
    const float* W3_root = (const float*)d_in[10];
    float* out = (float*)d_out;

    float *agg, *h1, *h2;
    int *cnt, *rowptr, *cursor, *srcs;
    __nv_bfloat16 *Bh, *Bl;
    cudaGetSymbolAddress((void**)&agg, g_agg);
    cudaGetSymbolAddress((void**)&h1, g_h1);
    cudaGetSymbolAddress((void**)&h2, g_h2);
    cudaGetSymbolAddress((void**)&cnt, g_cnt);
    cudaGetSymbolAddress((void**)&rowptr, g_rowptr);
    cudaGetSymbolAddress((void**)&cursor, g_cursor);
    cudaGetSymbolAddress((void**)&srcs, g_srcs);
    cudaGetSymbolAddress((void**)&Bh, g_Bh);
    cudaGetSymbolAddress((void**)&Bl, g_Bl);

    // CSR build (edge_index identical for all 3 layers)
    zero_cnt_kernel<<<(N_NODES + 255) / 256, 256>>>(cnt);
    hist_kernel<<<(E_EDGES + 255) / 256, 256>>>(ei, cnt);
    scan_kernel<<<1, 1024>>>(cnt, rowptr, cursor);
    fill_kernel<<<(E_EDGES + 255) / 256, 256>>>(ei, cursor, srcs);
    // Weight prep (hi/lo bf16 planes, [k][n])
    prep_weights<<<(3 * KTOT * DIM + 255) / 256, 256>>>(
        W1_rel, W1_root, W2_rel, W2_root, W3_rel, W3_root, Bh, Bl);

    run_layer(x,  Bh,               Bl,               b1, rowptr, srcs, agg, h1);
    run_layer(h1, Bh + KTOT * DIM,  Bl + KTOT * DIM,  b2, rowptr, srcs, agg, h2);
    run_layer(h2, Bh + 2 * KTOT * DIM, Bl + 2 * KTOT * DIM, b3, rowptr, srcs, agg, out);
}